// round 8
// baseline (speedup 1.0000x reference)
#include <cuda_runtime.h>
#include <cuda_bf16.h>

// Fused Conv3d(8->8, k=3, same zero-pad) + sigmoid(gelu_tanh(relu(y))) + bias
// B=8, D=32, H=128, W=128. fp32, packed f32x2 FMAs.
//
// Round-8: remove the W-shifted SMEM copy (sS). Shifted operand pairs are
// built in registers per kh-iter: 2 aligned LDS.128 + 2 warp shuffles for the
// W halo + 5 mov.b64 pairs. Cuts hot-loop SMEM wavefronts 18->8 per warp/kh
// and removes the second staging store. ALU/SHFL pipes absorb the cost (were
// ~13% busy). 128-thr CTAs, 4/SM; weights in __constant__.

#define ROWP 132   // padded row stride in floats
#define TH   8     // H rows per CTA

typedef unsigned long long u64;

__constant__ __align__(16) u64 cW[1728];     // splatted (w,w), [(ci*3+kd)*3+kh][kw*8+co]
__device__   __align__(16) u64 gW_buf[1728]; // staging buffer for the memcpy node

__device__ __forceinline__ void fma2(u64& d, u64 a, u64 b) {
    asm("fma.rn.f32x2 %0, %1, %2, %0;" : "+l"(d) : "l"(a), "l"(b));
}
__device__ __forceinline__ u64 pk2(float lo, float hi) {
    u64 r;
    asm("mov.b64 %0, {%1, %2};" : "=l"(r) : "f"(lo), "f"(hi));
    return r;
}
__device__ __forceinline__ float2 up2(u64 v) {
    float lo, hi;
    asm("mov.b64 {%0, %1}, %2;" : "=f"(lo), "=f"(hi) : "l"(v));
    return make_float2(lo, hi);
}

// sigmoid(gelu_tanh(relu(y))): for yr=relu(y)>=0,
//   gelu = 0.5*yr*(1+tanh(t)) = yr * sigmoid(2t),  t = 0.79788456*(yr + 0.044715*yr^3)
__device__ __forceinline__ float act_chain(float y) {
    float yr = fmaxf(y, 0.0f);
    float q  = fmaf(0.044715f * yr, yr, 1.0f);
    float t2 = 1.5957691216057308f * yr * q;          // 2*t
    float g  = yr * __fdividef(1.0f, 1.0f + __expf(-t2));
    return __fdividef(1.0f, 1.0f + __expf(-g));
}

__global__ void weight_splat_kernel(const float* __restrict__ wgt) {
    for (int i = threadIdx.x; i < 1728; i += 256) {
        int co  = i / 216;  int rem = i - co * 216;
        int ci  = rem / 27; int r2  = rem - ci * 27;
        int kd  = r2 / 9;   int r3  = r2 - kd * 9;
        int kh  = r3 / 3;   int kw  = r3 - kh * 3;
        float w = wgt[i];   // layout [co][ci][kd][kh][kw] linear == i
        gW_buf[((ci * 3 + kd) * 3 + kh) * 24 + kw * 8 + co] = pk2(w, w);
    }
}

__global__ void __launch_bounds__(128, 4)
conv3d_fused_kernel(const float* __restrict__ x,
                    const float* __restrict__ bias,
                    float* __restrict__ out)
{
    __shared__ __align__(16) float sC[(TH + 2) * ROWP];   // sC[r][w] = x[r][w]

    const int tid  = threadIdx.x;
    const int lane = tid & 31;
    const int bx   = blockIdx.x;
    const int ht   = bx & 15;           // 16 H tiles of 8 rows
    const int dpos = (bx >> 4) & 31;
    const int b    = bx >> 9;
    const int h0   = ht << 3;

    const int hh = tid >> 4;     // row in tile (0..7)
    const int wg = tid & 15;
    const int w0 = wg << 3;
    const bool wlo = (wg == 0);
    const bool whi = (wg == 15);

    u64 acc[32];
    #pragma unroll
    for (int k = 0; k < 32; ++k) acc[k] = 0ull;

    for (int ci = 0; ci < 8; ++ci) {
        const float* xb = x + ((size_t)((b * 8 + ci) * 32) << 14);
        #pragma unroll 1
        for (int dz = 0; dz < 3; ++dz) {
            const int dd = dpos + dz - 1;
            if ((unsigned)dd >= 32u) continue;   // zero slice contributes nothing

            __syncthreads();  // previous slab fully consumed

            // stage (TH+2) rows x 128 cols: plain LDG.128 -> STS.128
            const float4* xs4 = reinterpret_cast<const float4*>(xb + ((size_t)dd << 14));
            #pragma unroll
            for (int j = 0; j < 3; ++j) {
                int i = tid + j * 128;           // 0..383, valid < 320
                int hz = i >> 5;                 // uniform within a warp
                if (hz < TH + 2) {
                    int hg = h0 + hz - 1;
                    float4 v = make_float4(0.f, 0.f, 0.f, 0.f);
                    if ((unsigned)hg < 128u) v = xs4[(hg << 5) + lane];
                    *reinterpret_cast<float4*>(&sC[hz * ROWP + (lane << 2)]) = v;
                }
            }
            __syncthreads();

            #pragma unroll
            for (int kh = 0; kh < 3; ++kh) {
                const int roff = (hh + kh) * ROWP;
                const ulonglong2* cp = reinterpret_cast<const ulonglong2*>(&sC[roff + w0]);
                ulonglong2 ca = cp[0];    // (x0,x1),(x2,x3)
                ulonglong2 cb = cp[1];    // (x4,x5),(x6,x7)
                float2 f01 = up2(ca.x), f23 = up2(ca.y);
                float2 f45 = up2(cb.x), f67 = up2(cb.y);
                // W halo via lane shuffles (lanes 0..15 / 16..31 are two rows)
                float xm1 = __shfl_up_sync(0xffffffffu, f67.y, 1);
                float xp8 = __shfl_down_sync(0xffffffffu, f01.x, 1);
                if (wlo) xm1 = 0.0f;
                if (whi) xp8 = 0.0f;
                // shifted pairs in registers
                u64 L0 = pk2(xm1,  f01.x);
                u64 L1 = pk2(f01.y, f23.x);
                u64 L2 = pk2(f23.y, f45.x);
                u64 L3 = pk2(f45.y, f67.x);
                u64 R3 = pk2(f67.y, xp8);

                const u64* wp = &cW[((ci * 3 + dz) * 3 + kh) * 24];
                #pragma unroll
                for (int cp2 = 0; cp2 < 4; ++cp2) {   // co pairs (2 couts each)
                    ulonglong2 wL = *reinterpret_cast<const ulonglong2*>(wp + 2 * cp2);
                    ulonglong2 wC = *reinterpret_cast<const ulonglong2*>(wp + 8 + 2 * cp2);
                    ulonglong2 wR = *reinterpret_cast<const ulonglong2*>(wp + 16 + 2 * cp2);
                    u64* a0 = &acc[(2 * cp2) * 4];
                    u64* a1 = &acc[(2 * cp2 + 1) * 4];
                    // center first (no shuffle dependency)
                    fma2(a0[0], ca.x, wC.x);  fma2(a0[1], ca.y, wC.x);
                    fma2(a0[2], cb.x, wC.x);  fma2(a0[3], cb.y, wC.x);
                    fma2(a1[0], ca.x, wC.y);  fma2(a1[1], ca.y, wC.y);
                    fma2(a1[2], cb.x, wC.y);  fma2(a1[3], cb.y, wC.y);
                    // left taps
                    fma2(a0[0], L0, wL.x);    fma2(a0[1], L1, wL.x);
                    fma2(a0[2], L2, wL.x);    fma2(a0[3], L3, wL.x);
                    fma2(a1[0], L0, wL.y);    fma2(a1[1], L1, wL.y);
                    fma2(a1[2], L2, wL.y);    fma2(a1[3], L3, wL.y);
                    // right taps
                    fma2(a0[0], L1, wR.x);    fma2(a0[1], L2, wR.x);
                    fma2(a0[2], L3, wR.x);    fma2(a0[3], R3, wR.x);
                    fma2(a1[0], L1, wR.y);    fma2(a1[1], L2, wR.y);
                    fma2(a1[2], L3, wR.y);    fma2(a1[3], R3, wR.y);
                }
            }
        }
    }

    // --- epilogue: activation chain + bias, vectorized coalesced stores ---
    const int hout = h0 + hh;
    #pragma unroll
    for (int co = 0; co < 8; ++co) {
        float bb = bias[co];
        float o[8];
        #pragma unroll
        for (int j = 0; j < 4; ++j) {
            float2 p = up2(acc[co * 4 + j]);
            o[2 * j]     = p.x;
            o[2 * j + 1] = p.y;
        }
        #pragma unroll
        for (int k = 0; k < 8; ++k)
            o[k] = act_chain(o[k]) + bb;

        float4* dst = reinterpret_cast<float4*>(
            out + ((size_t)((b * 8 + co) * 32 + dpos) << 14) + (hout << 7) + w0);
        dst[0] = make_float4(o[0], o[1], o[2], o[3]);
        dst[1] = make_float4(o[4], o[5], o[6], o[7]);
    }
}

extern "C" void kernel_launch(void* const* d_in, const int* in_sizes, int n_in,
                              void* d_out, int out_size)
{
    const float* x    = (const float*)d_in[0];   // (8,8,32,128,128)
    const float* wgt  = (const float*)d_in[1];   // (8,8,3,3,3)
    const float* bias = (const float*)d_in[2];   // (8,1,1,1)
    float* out = (float*)d_out;                  // (8,8,32,128,128)

    weight_splat_kernel<<<1, 256>>>(wgt);
    void* gw_ptr = nullptr;
    cudaGetSymbolAddress(&gw_ptr, gW_buf);
    cudaMemcpyToSymbolAsync(cW, gw_ptr, 1728 * sizeof(u64), 0,
                            cudaMemcpyDeviceToDevice, 0);
    // grid = 16 H-tiles * 32 depths * 8 batches = 4096 blocks of 128 threads
    conv3d_fused_kernel<<<4096, 128>>>(x, bias, out);
}

// round 9
// speedup vs baseline: 1.8288x; 1.8288x over previous
#include <cuda_runtime.h>
#include <cuda_bf16.h>

// Fused Conv3d(8->8, k=3, same zero-pad) + sigmoid(gelu_tanh(relu(y))) + bias
// B=8, D=32, H=128, W=128. fp32, packed f32x2 FMAs.
//
// Round-9: R7 base + thread-level H reuse. Each thread computes 2 output H
// rows x 4 W pixels x 8 couts (32 u64 accs, unchanged). Each staged slab row
// now feeds TWO (output,kh) pairs, cutting hot-loop SMEM loads 15->12 per
// slab (wf 54->40 per warp). Rolling 2-row register window; all f32x2
// operands remain memory-aligned pairs (hard rule: pk2-built operands cause
// ALU blowup, see R1/R8). 128-thr CTAs, 4/SM; weights in __constant__.

#define ROWP 132   // padded row stride in floats
#define TH   8     // H rows per CTA

typedef unsigned long long u64;

__constant__ __align__(16) u64 cW[1728];     // splatted (w,w), [(ci*3+kd)*3+kh][kw*8+co]
__device__   __align__(16) u64 gW_buf[1728]; // staging buffer for the memcpy node

__device__ __forceinline__ void fma2(u64& d, u64 a, u64 b) {
    asm("fma.rn.f32x2 %0, %1, %2, %0;" : "+l"(d) : "l"(a), "l"(b));
}
__device__ __forceinline__ u64 pk2(float lo, float hi) {
    u64 r;
    asm("mov.b64 %0, {%1, %2};" : "=l"(r) : "f"(lo), "f"(hi));
    return r;
}
__device__ __forceinline__ float2 up2(u64 v) {
    float lo, hi;
    asm("mov.b64 {%0, %1}, %2;" : "=f"(lo), "=f"(hi) : "l"(v));
    return make_float2(lo, hi);
}

// sigmoid(gelu_tanh(relu(y))): for yr=relu(y)>=0,
//   gelu = 0.5*yr*(1+tanh(t)) = yr * sigmoid(2t),  t = 0.79788456*(yr + 0.044715*yr^3)
__device__ __forceinline__ float act_chain(float y) {
    float yr = fmaxf(y, 0.0f);
    float q  = fmaf(0.044715f * yr, yr, 1.0f);
    float t2 = 1.5957691216057308f * yr * q;          // 2*t
    float g  = yr * __fdividef(1.0f, 1.0f + __expf(-t2));
    return __fdividef(1.0f, 1.0f + __expf(-g));
}

__global__ void weight_splat_kernel(const float* __restrict__ wgt) {
    for (int i = threadIdx.x; i < 1728; i += 256) {
        int co  = i / 216;  int rem = i - co * 216;
        int ci  = rem / 27; int r2  = rem - ci * 27;
        int kd  = r2 / 9;   int r3  = r2 - kd * 9;
        int kh  = r3 / 3;   int kw  = r3 - kh * 3;
        float w = wgt[i];   // layout [co][ci][kd][kh][kw] linear == i
        gW_buf[((ci * 3 + kd) * 3 + kh) * 24 + kw * 8 + co] = pk2(w, w);
    }
}

// 12 packed FMAs: one output row, one kh, 2 couts (wL/wC/wR .x/.y), 2 pixel pairs
__device__ __forceinline__ void conv_out(u64* A, const ulonglong2& ca,
                                         const ulonglong2& sa, u64 r1,
                                         const ulonglong2& wL, const ulonglong2& wC,
                                         const ulonglong2& wR) {
    fma2(A[0], sa.x, wL.x);  fma2(A[1], sa.y, wL.x);
    fma2(A[0], ca.x, wC.x);  fma2(A[1], ca.y, wC.x);
    fma2(A[0], sa.y, wR.x);  fma2(A[1], r1,   wR.x);
    fma2(A[2], sa.x, wL.y);  fma2(A[3], sa.y, wL.y);
    fma2(A[2], ca.x, wC.y);  fma2(A[3], ca.y, wC.y);
    fma2(A[2], sa.y, wR.y);  fma2(A[3], r1,   wR.y);
}

__global__ void __launch_bounds__(128, 4)
conv3d_fused_kernel(const float* __restrict__ x,
                    const float* __restrict__ bias,
                    float* __restrict__ out)
{
    __shared__ __align__(16) float sC[(TH + 2) * ROWP];   // sC[r][w] = x[r][w]
    __shared__ __align__(16) float sS[(TH + 2) * ROWP];   // sS[r][k] = x[r][k-1]

    const int tid  = threadIdx.x;
    const int lane = tid & 31;
    const int warp = tid >> 5;          // 0..3 -> output row pair
    const int bx   = blockIdx.x;
    const int ht   = bx & 15;           // 16 H tiles of 8 rows
    const int dpos = (bx >> 4) & 31;
    const int b    = bx >> 9;
    const int h0   = ht << 3;

    // k=129 pad of the shifted copy (never rewritten; k=0 written each slab)
    if (tid < TH + 2) sS[tid * ROWP + 129] = 0.0f;

    const int hr0 = warp << 1;   // first of 2 output rows (slab-row base too)
    const int w0  = lane << 2;   // 4 pixels per thread

    u64 acc0[16], acc1[16];      // [cp2*4 + {coutA p0,p1, coutB p0,p1}]
    #pragma unroll
    for (int k = 0; k < 16; ++k) { acc0[k] = 0ull; acc1[k] = 0ull; }

    for (int ci = 0; ci < 8; ++ci) {
        const float* xb = x + ((size_t)((b * 8 + ci) * 32) << 14);
        #pragma unroll 1
        for (int dz = 0; dz < 3; ++dz) {
            const int dd = dpos + dz - 1;
            if ((unsigned)dd >= 32u) continue;   // zero slice contributes nothing

            __syncthreads();  // previous slab fully consumed

            // single-pass staging: (TH+2) rows x 128 cols; each warp stages a
            // full row per iteration, writing sC and the lane-rotated sS.
            const float4* xs4 = reinterpret_cast<const float4*>(xb + ((size_t)dd << 14));
            #pragma unroll
            for (int j = 0; j < 3; ++j) {
                int i = tid + j * 128;           // 0..383, valid < 320
                int hz = i >> 5;                 // uniform within a warp
                bool rowok = hz < TH + 2;
                int hg = h0 + hz - 1;
                float4 v = make_float4(0.f, 0.f, 0.f, 0.f);
                if (rowok && (unsigned)hg < 128u) v = xs4[(hg << 5) + lane];
                float pw = __shfl_up_sync(0xffffffffu, v.w, 1);
                if (lane == 0) pw = 0.0f;        // x[-1] zero pad
                if (rowok) {
                    float* rowC = &sC[hz * ROWP];
                    float* rowS = &sS[hz * ROWP];
                    *reinterpret_cast<float4*>(rowC + (lane << 2)) = v;
                    *reinterpret_cast<float4*>(rowS + (lane << 2)) =
                        make_float4(pw, v.x, v.y, v.z);
                    if (lane == 31) rowS[128] = v.w;   // sS[128] = x[127]
                }
            }
            __syncthreads();

            // rolling 2-row window over slab rows hr0 .. hr0+3
            const u64* wbase = &cW[(ci * 3 + dz) * 72];
            ulonglong2 caA, saA, caB, saB;
            u64 r1A, r1B;
            {
                int off = hr0 * ROWP + w0;
                caA = *reinterpret_cast<const ulonglong2*>(&sC[off]);
                saA = *reinterpret_cast<const ulonglong2*>(&sS[off]);
                r1A = *reinterpret_cast<const u64*>(&sS[off + 4]);
                off += ROWP;
                caB = *reinterpret_cast<const ulonglong2*>(&sC[off]);
                saB = *reinterpret_cast<const ulonglong2*>(&sS[off]);
                r1B = *reinterpret_cast<const u64*>(&sS[off + 4]);
            }
            #pragma unroll
            for (int kh = 0; kh < 3; ++kh) {
                const u64* wp = wbase + kh * 24;
                #pragma unroll
                for (int cp2 = 0; cp2 < 4; ++cp2) {
                    ulonglong2 wL = *reinterpret_cast<const ulonglong2*>(wp + 2 * cp2);
                    ulonglong2 wC = *reinterpret_cast<const ulonglong2*>(wp + 8 + 2 * cp2);
                    ulonglong2 wR = *reinterpret_cast<const ulonglong2*>(wp + 16 + 2 * cp2);
                    conv_out(&acc0[cp2 * 4], caA, saA, r1A, wL, wC, wR); // out row hr0,  row hr0+kh
                    conv_out(&acc1[cp2 * 4], caB, saB, r1B, wL, wC, wR); // out row hr0+1, row hr0+1+kh
                }
                if (kh < 2) {
                    caA = caB; saA = saB; r1A = r1B;    // renamed away by unroll
                    int off = (hr0 + kh + 2) * ROWP + w0;
                    caB = *reinterpret_cast<const ulonglong2*>(&sC[off]);
                    saB = *reinterpret_cast<const ulonglong2*>(&sS[off]);
                    r1B = *reinterpret_cast<const u64*>(&sS[off + 4]);
                }
            }
        }
    }

    // --- epilogue: activation chain + bias, vectorized coalesced stores ---
    #pragma unroll
    for (int co = 0; co < 8; ++co) {
        float bb = bias[co];
        const int cp2 = co >> 1, sub = (co & 1) * 2;
        const size_t cbase = ((size_t)((b * 8 + co) * 32 + dpos) << 14) + w0;
        #pragma unroll
        for (int o = 0; o < 2; ++o) {
            const u64* A = (o == 0) ? acc0 : acc1;
            float2 p0 = up2(A[cp2 * 4 + sub]);
            float2 p1 = up2(A[cp2 * 4 + sub + 1]);
            float4 r;
            r.x = act_chain(p0.x) + bb;
            r.y = act_chain(p0.y) + bb;
            r.z = act_chain(p1.x) + bb;
            r.w = act_chain(p1.y) + bb;
            *reinterpret_cast<float4*>(out + cbase + ((h0 + hr0 + o) << 7)) = r;
        }
    }
}

extern "C" void kernel_launch(void* const* d_in, const int* in_sizes, int n_in,
                              void* d_out, int out_size)
{
    const float* x    = (const float*)d_in[0];   // (8,8,32,128,128)
    const float* wgt  = (const float*)d_in[1];   // (8,8,3,3,3)
    const float* bias = (const float*)d_in[2];   // (8,1,1,1)
    float* out = (float*)d_out;                  // (8,8,32,128,128)

    weight_splat_kernel<<<1, 256>>>(wgt);
    void* gw_ptr = nullptr;
    cudaGetSymbolAddress(&gw_ptr, gW_buf);
    cudaMemcpyToSymbolAsync(cW, gw_ptr, 1728 * sizeof(u64), 0,
                            cudaMemcpyDeviceToDevice, 0);
    // grid = 16 H-tiles * 32 depths * 8 batches = 4096 blocks of 128 threads
    conv3d_fused_kernel<<<4096, 128>>>(x, bias, out);
}

// round 10
// speedup vs baseline: 1.9165x; 1.0480x over previous
#include <cuda_runtime.h>
#include <cuda_bf16.h>

// Fused Conv3d(8->8, k=3, same zero-pad) + sigmoid(gelu_tanh(relu(y))) + bias
// B=8, D=32, H=128, W=128. fp32, packed f32x2 FMAs.
//
// Round-10 (R9 base):
//  - merged staging: all 3 depth slices of a cin staged at once -> one
//    barrier pair per cin (16 total instead of 48), deep LDG MLP per pass.
//  - epilogue uses tanh.approx.f32 (2 MUFU/elem instead of 4).
// Thread: 2 output H rows x 4 W pixels x 8 couts (32 u64 accs). All f32x2
// operands are memory-aligned pairs (pk2-built operands cause ALU blowup).
// 128-thr CTAs, 4/SM; weights in __constant__.

#define ROWP 132   // padded row stride in floats
#define TH   8     // H rows per CTA
#define SLROWS 10  // rows per staged slice (TH + 2)

typedef unsigned long long u64;

__constant__ __align__(16) u64 cW[1728];     // splatted (w,w), [(ci*3+kd)*3+kh][kw*8+co]
__device__   __align__(16) u64 gW_buf[1728]; // staging buffer for the memcpy node

__device__ __forceinline__ void fma2(u64& d, u64 a, u64 b) {
    asm("fma.rn.f32x2 %0, %1, %2, %0;" : "+l"(d) : "l"(a), "l"(b));
}
__device__ __forceinline__ u64 pk2(float lo, float hi) {
    u64 r;
    asm("mov.b64 %0, {%1, %2};" : "=l"(r) : "f"(lo), "f"(hi));
    return r;
}
__device__ __forceinline__ float2 up2(u64 v) {
    float lo, hi;
    asm("mov.b64 {%0, %1}, %2;" : "=f"(lo), "=f"(hi) : "l"(v));
    return make_float2(lo, hi);
}
__device__ __forceinline__ float tanhapx(float x) {
    float r;
    asm("tanh.approx.f32 %0, %1;" : "=f"(r) : "f"(x));
    return r;
}

// sigmoid(gelu_tanh(relu(y))) via 2x tanh.approx:
//   yr = relu(y); gelu = 0.5*yr*(1+tanh(t)), t = 0.79788456*(yr+0.044715*yr^3)
//   sigmoid(g) = 0.5*tanh(g/2) + 0.5
__device__ __forceinline__ float act_chain(float y) {
    float yr = fmaxf(y, 0.0f);
    float q  = fmaf(0.044715f * yr, yr, 1.0f);
    float t  = 0.7978845608028654f * yr * q;
    float hyr = 0.5f * yr;
    float g  = fmaf(hyr, tanhapx(t), hyr);
    return fmaf(0.5f, tanhapx(0.5f * g), 0.5f);
}

__global__ void weight_splat_kernel(const float* __restrict__ wgt) {
    for (int i = threadIdx.x; i < 1728; i += 256) {
        int co  = i / 216;  int rem = i - co * 216;
        int ci  = rem / 27; int r2  = rem - ci * 27;
        int kd  = r2 / 9;   int r3  = r2 - kd * 9;
        int kh  = r3 / 3;   int kw  = r3 - kh * 3;
        float w = wgt[i];   // layout [co][ci][kd][kh][kw] linear == i
        gW_buf[((ci * 3 + kd) * 3 + kh) * 24 + kw * 8 + co] = pk2(w, w);
    }
}

// 12 packed FMAs: one output row, one kh, 2 couts, 2 pixel pairs
__device__ __forceinline__ void conv_out(u64* A, const ulonglong2& ca,
                                         const ulonglong2& sa, u64 r1,
                                         const ulonglong2& wL, const ulonglong2& wC,
                                         const ulonglong2& wR) {
    fma2(A[0], sa.x, wL.x);  fma2(A[1], sa.y, wL.x);
    fma2(A[0], ca.x, wC.x);  fma2(A[1], ca.y, wC.x);
    fma2(A[0], sa.y, wR.x);  fma2(A[1], r1,   wR.x);
    fma2(A[2], sa.x, wL.y);  fma2(A[3], sa.y, wL.y);
    fma2(A[2], ca.x, wC.y);  fma2(A[3], ca.y, wC.y);
    fma2(A[2], sa.y, wR.y);  fma2(A[3], r1,   wR.y);
}

__global__ void __launch_bounds__(128, 4)
conv3d_fused_kernel(const float* __restrict__ x,
                    const float* __restrict__ bias,
                    float* __restrict__ out)
{
    __shared__ __align__(16) float sC[3 * SLROWS * ROWP];  // 3 slices, x[r][w]
    __shared__ __align__(16) float sS[3 * SLROWS * ROWP];  // shifted: sS[r][k]=x[r][k-1]

    const int tid  = threadIdx.x;
    const int lane = tid & 31;
    const int warp = tid >> 5;          // 0..3 -> output row pair
    const int bx   = blockIdx.x;
    const int ht   = bx & 15;           // 16 H tiles of 8 rows
    const int dpos = (bx >> 4) & 31;
    const int b    = bx >> 9;
    const int h0   = ht << 3;

    // k=129 pads of the shifted copy (staging writes only k=0..128)
    if (tid < 3 * SLROWS) sS[tid * ROWP + 129] = 0.0f;

    const int hr0 = warp << 1;   // first of 2 output rows within tile
    const int w0  = lane << 2;   // 4 pixels per thread

    u64 acc0[16], acc1[16];      // [cp2*4 + {coutA p0,p1, coutB p0,p1}]
    #pragma unroll
    for (int k = 0; k < 16; ++k) { acc0[k] = 0ull; acc1[k] = 0ull; }

    const int dlo = (dpos == 0)  ? 1 : 0;   // valid dz range (uniform)
    const int dhi = (dpos == 31) ? 2 : 3;

    for (int ci = 0; ci < 8; ++ci) {
        __syncthreads();   // previous ci's slabs fully consumed (pads on iter 0)

        // --- stage all 3 slices (dpos-1 .. dpos+1), 30 rows x 128 cols ---
        const float4* xc4 = reinterpret_cast<const float4*>(x) +
                            ((size_t)(b * 8 + ci) << 17);   // *32*4096
        #pragma unroll
        for (int j = 0; j < 8; ++j) {
            int i = tid + j * 128;            // 0..1023, valid < 960
            if (i < 960) {
                int rowg = i >> 5;            // 0..29, uniform per warp
                int sz   = rowg / 10;         // slice (dz)
                int hz   = rowg - sz * 10;
                int dd   = dpos + sz - 1;
                int hg   = h0 + hz - 1;
                float4 v = make_float4(0.f, 0.f, 0.f, 0.f);
                if ((unsigned)dd < 32u && (unsigned)hg < 128u)
                    v = xc4[(dd << 12) + (hg << 5) + lane];
                float pw = __shfl_up_sync(0xffffffffu, v.w, 1);
                if (lane == 0) pw = 0.0f;     // x[-1] zero pad
                float* rowC = &sC[rowg * ROWP];
                float* rowS = &sS[rowg * ROWP];
                *reinterpret_cast<float4*>(rowC + (lane << 2)) = v;
                *reinterpret_cast<float4*>(rowS + (lane << 2)) =
                    make_float4(pw, v.x, v.y, v.z);
                if (lane == 31) rowS[128] = v.w;   // sS[128] = x[127]
            }
        }
        __syncthreads();

        // --- compute: 3 depth taps from the staged block ---
        #pragma unroll 1
        for (int dz = dlo; dz < dhi; ++dz) {
            const float* scb = &sC[dz * SLROWS * ROWP];
            const float* ssb = &sS[dz * SLROWS * ROWP];
            const u64* wbase = &cW[(ci * 3 + dz) * 72];

            ulonglong2 caA, saA, caB, saB;
            u64 r1A, r1B;
            {
                int off = hr0 * ROWP + w0;
                caA = *reinterpret_cast<const ulonglong2*>(&scb[off]);
                saA = *reinterpret_cast<const ulonglong2*>(&ssb[off]);
                r1A = *reinterpret_cast<const u64*>(&ssb[off + 4]);
                off += ROWP;
                caB = *reinterpret_cast<const ulonglong2*>(&scb[off]);
                saB = *reinterpret_cast<const ulonglong2*>(&ssb[off]);
                r1B = *reinterpret_cast<const u64*>(&ssb[off + 4]);
            }
            #pragma unroll
            for (int kh = 0; kh < 3; ++kh) {
                const u64* wp = wbase + kh * 24;
                #pragma unroll
                for (int cp2 = 0; cp2 < 4; ++cp2) {
                    ulonglong2 wL = *reinterpret_cast<const ulonglong2*>(wp + 2 * cp2);
                    ulonglong2 wC = *reinterpret_cast<const ulonglong2*>(wp + 8 + 2 * cp2);
                    ulonglong2 wR = *reinterpret_cast<const ulonglong2*>(wp + 16 + 2 * cp2);
                    conv_out(&acc0[cp2 * 4], caA, saA, r1A, wL, wC, wR);
                    conv_out(&acc1[cp2 * 4], caB, saB, r1B, wL, wC, wR);
                }
                if (kh < 2) {
                    caA = caB; saA = saB; r1A = r1B;    // renamed away by unroll
                    int off = (hr0 + kh + 2) * ROWP + w0;
                    caB = *reinterpret_cast<const ulonglong2*>(&scb[off]);
                    saB = *reinterpret_cast<const ulonglong2*>(&ssb[off]);
                    r1B = *reinterpret_cast<const u64*>(&ssb[off + 4]);
                }
            }
        }
    }

    // --- epilogue: activation chain + bias, vectorized coalesced stores ---
    #pragma unroll
    for (int co = 0; co < 8; ++co) {
        float bb = bias[co];
        const int cp2 = co >> 1, sub = (co & 1) * 2;
        const size_t cbase = ((size_t)((b * 8 + co) * 32 + dpos) << 14) + w0;
        #pragma unroll
        for (int o = 0; o < 2; ++o) {
            const u64* A = (o == 0) ? acc0 : acc1;
            float2 p0 = up2(A[cp2 * 4 + sub]);
            float2 p1 = up2(A[cp2 * 4 + sub + 1]);
            float4 r;
            r.x = act_chain(p0.x) + bb;
            r.y = act_chain(p0.y) + bb;
            r.z = act_chain(p1.x) + bb;
            r.w = act_chain(p1.y) + bb;
            *reinterpret_cast<float4*>(out + cbase + ((h0 + hr0 + o) << 7)) = r;
        }
    }
}

extern "C" void kernel_launch(void* const* d_in, const int* in_sizes, int n_in,
                              void* d_out, int out_size)
{
    const float* x    = (const float*)d_in[0];   // (8,8,32,128,128)
    const float* wgt  = (const float*)d_in[1];   // (8,8,3,3,3)
    const float* bias = (const float*)d_in[2];   // (8,1,1,1)
    float* out = (float*)d_out;                  // (8,8,32,128,128)

    weight_splat_kernel<<<1, 256>>>(wgt);
    void* gw_ptr = nullptr;
    cudaGetSymbolAddress(&gw_ptr, gW_buf);
    cudaMemcpyToSymbolAsync(cW, gw_ptr, 1728 * sizeof(u64), 0,
                            cudaMemcpyDeviceToDevice, 0);
    // grid = 16 H-tiles * 32 depths * 8 batches = 4096 blocks of 128 threads
    conv3d_fused_kernel<<<4096, 128>>>(x, bias, out);
}

// round 11
// speedup vs baseline: 1.9308x; 1.0075x over previous
#include <cuda_runtime.h>
#include <cuda_bf16.h>

// Fused Conv3d(8->8, k=3, same zero-pad) + sigmoid(gelu_tanh(relu(y))) + bias
// B=8, D=32, H=128, W=128. fp32, packed f32x2 FMAs.
//
// Round-11 (R10 base): ci-granularity cp.async double-buffering.
//  - sC ping-pong filled by cp.async.cg; the fill for ci+1 is issued right
//    after ci's wait+barrier, overlapping ci's ~1700 cycles of FMA compute.
//  - sS (W-shifted copy) single-buffered, rebuilt per ci from sC[p] via
//    LDS.128 -> shfl -> STS.128 (SMEM latency instead of exposed GMEM).
// Thread: 2 output H rows x 4 W pixels x 8 couts. All f32x2 operands are
// memory-aligned pairs. 128-thr CTAs, 4/SM; weights in __constant__.

#define ROWP 132     // padded row stride in floats
#define TH   8       // H rows per CTA
#define SLROWS 10    // rows per staged slice
#define NROWS 30     // 3 slices

typedef unsigned long long u64;

__constant__ __align__(16) u64 cW[1728];     // splatted (w,w), [(ci*3+kd)*3+kh][kw*8+co]
__device__   __align__(16) u64 gW_buf[1728];

__device__ __forceinline__ void fma2(u64& d, u64 a, u64 b) {
    asm("fma.rn.f32x2 %0, %1, %2, %0;" : "+l"(d) : "l"(a), "l"(b));
}
__device__ __forceinline__ u64 pk2(float lo, float hi) {
    u64 r;
    asm("mov.b64 %0, {%1, %2};" : "=l"(r) : "f"(lo), "f"(hi));
    return r;
}
__device__ __forceinline__ float2 up2(u64 v) {
    float lo, hi;
    asm("mov.b64 {%0, %1}, %2;" : "=f"(lo), "=f"(hi) : "l"(v));
    return make_float2(lo, hi);
}
__device__ __forceinline__ float tanhapx(float x) {
    float r;
    asm("tanh.approx.f32 %0, %1;" : "=f"(r) : "f"(x));
    return r;
}

// sigmoid(gelu_tanh(relu(y))) via 2x tanh.approx
__device__ __forceinline__ float act_chain(float y) {
    float yr = fmaxf(y, 0.0f);
    float q  = fmaf(0.044715f * yr, yr, 1.0f);
    float t  = 0.7978845608028654f * yr * q;
    float hyr = 0.5f * yr;
    float g  = fmaf(hyr, tanhapx(t), hyr);
    return fmaf(0.5f, tanhapx(0.5f * g), 0.5f);
}

__global__ void weight_splat_kernel(const float* __restrict__ wgt) {
    for (int i = threadIdx.x; i < 1728; i += 256) {
        int co  = i / 216;  int rem = i - co * 216;
        int ci  = rem / 27; int r2  = rem - ci * 27;
        int kd  = r2 / 9;   int r3  = r2 - kd * 9;
        int kh  = r3 / 3;   int kw  = r3 - kh * 3;
        float w = wgt[i];
        gW_buf[((ci * 3 + kd) * 3 + kh) * 24 + kw * 8 + co] = pk2(w, w);
    }
}

// issue cp.async fill of one 30x128 block (3 slices of cin ci) into dst
__device__ __forceinline__ void stage_issue(float* dst, const float* __restrict__ x,
                                            int b, int ci, int dpos, int h0,
                                            int tid, int lane) {
    const float4* xc4 = reinterpret_cast<const float4*>(x) +
                        ((size_t)(b * 8 + ci) << 17);   // * 32 * 4096
    #pragma unroll
    for (int j = 0; j < 8; ++j) {
        int i = tid + j * 128;                // 0..1023, valid < 960
        if (i < 960) {
            int rowg = i >> 5;                // 0..29
            int sz   = rowg / 10;
            int hz   = rowg - sz * 10;
            int dd   = dpos + sz - 1;
            int hg   = h0 + hz - 1;
            bool ok = ((unsigned)dd < 32u) && ((unsigned)hg < 128u);
            const float4* src = xc4 + (((ok ? dd : 0) << 12) + ((ok ? hg : 0) << 5) + lane);
            unsigned d = (unsigned)__cvta_generic_to_shared(dst + rowg * ROWP + (lane << 2));
            int nbytes = ok ? 16 : 0;         // 0 => zero-fill (D/H pad)
            asm volatile("cp.async.cg.shared.global [%0], [%1], 16, %2;"
                         :: "r"(d), "l"(src), "r"(nbytes));
        }
    }
    asm volatile("cp.async.commit_group;");
}

// 12 packed FMAs: one output row, one kh, 2 couts, 2 pixel pairs
__device__ __forceinline__ void conv_out(u64* A, const ulonglong2& ca,
                                         const ulonglong2& sa, u64 r1,
                                         const ulonglong2& wL, const ulonglong2& wC,
                                         const ulonglong2& wR) {
    fma2(A[0], sa.x, wL.x);  fma2(A[1], sa.y, wL.x);
    fma2(A[0], ca.x, wC.x);  fma2(A[1], ca.y, wC.x);
    fma2(A[0], sa.y, wR.x);  fma2(A[1], r1,   wR.x);
    fma2(A[2], sa.x, wL.y);  fma2(A[3], sa.y, wL.y);
    fma2(A[2], ca.x, wC.y);  fma2(A[3], ca.y, wC.y);
    fma2(A[2], sa.y, wR.y);  fma2(A[3], r1,   wR.y);
}

__global__ void __launch_bounds__(128, 4)
conv3d_fused_kernel(const float* __restrict__ x,
                    const float* __restrict__ bias,
                    float* __restrict__ out)
{
    __shared__ __align__(16) float sC[2][NROWS * ROWP];  // ping-pong, x[r][w]
    __shared__ __align__(16) float sS[NROWS * ROWP];     // sS[r][k] = x[r][k-1]

    const int tid  = threadIdx.x;
    const int lane = tid & 31;
    const int warp = tid >> 5;
    const int bx   = blockIdx.x;
    const int ht   = bx & 15;
    const int dpos = (bx >> 4) & 31;
    const int b    = bx >> 9;
    const int h0   = ht << 3;

    // k=129 pads of sS (build pass writes only k=0..128)
    if (tid < NROWS) sS[tid * ROWP + 129] = 0.0f;

    const int hr0 = warp << 1;   // first of 2 output rows within tile
    const int w0  = lane << 2;   // 4 pixels per thread

    u64 acc0[16], acc1[16];
    #pragma unroll
    for (int k = 0; k < 16; ++k) { acc0[k] = 0ull; acc1[k] = 0ull; }

    const int dlo = (dpos == 0)  ? 1 : 0;
    const int dhi = (dpos == 31) ? 2 : 3;

    // prologue: fill buffer 0 with ci=0
    stage_issue(sC[0], x, b, 0, dpos, h0, tid, lane);

    for (int ci = 0; ci < 8; ++ci) {
        const int p = ci & 1;
        const float* scfull = sC[p];

        asm volatile("cp.async.wait_group 0;");   // ci's block landed
        __syncthreads();                          // + prev compute done (sS free)

        // prefetch ci+1 into the other buffer (overlaps sS build + compute)
        if (ci < 7)
            stage_issue(sC[1 - p], x, b, ci + 1, dpos, h0, tid, lane);

        // build sS[r][k+1] = scfull[r][k] (30 rows, 4 warps)
        #pragma unroll
        for (int j = 0; j < 8; ++j) {
            int row = warp + (j << 2);            // 0..31, valid < 30
            if (row < NROWS) {
                float4 v = *reinterpret_cast<const float4*>(
                    &scfull[row * ROWP + (lane << 2)]);
                float pw = __shfl_up_sync(0xffffffffu, v.w, 1);
                if (lane == 0) pw = 0.0f;         // x[-1] zero pad
                *reinterpret_cast<float4*>(&sS[row * ROWP + (lane << 2)]) =
                    make_float4(pw, v.x, v.y, v.z);
                if (lane == 31) sS[row * ROWP + 128] = v.w;
            }
        }
        __syncthreads();

        // compute: 3 depth taps from the staged block
        #pragma unroll 1
        for (int dz = dlo; dz < dhi; ++dz) {
            const float* scb = &scfull[dz * SLROWS * ROWP];
            const float* ssb = &sS[dz * SLROWS * ROWP];
            const u64* wbase = &cW[(ci * 3 + dz) * 72];

            ulonglong2 caA, saA, caB, saB;
            u64 r1A, r1B;
            {
                int off = hr0 * ROWP + w0;
                caA = *reinterpret_cast<const ulonglong2*>(&scb[off]);
                saA = *reinterpret_cast<const ulonglong2*>(&ssb[off]);
                r1A = *reinterpret_cast<const u64*>(&ssb[off + 4]);
                off += ROWP;
                caB = *reinterpret_cast<const ulonglong2*>(&scb[off]);
                saB = *reinterpret_cast<const ulonglong2*>(&ssb[off]);
                r1B = *reinterpret_cast<const u64*>(&ssb[off + 4]);
            }
            #pragma unroll
            for (int kh = 0; kh < 3; ++kh) {
                const u64* wp = wbase + kh * 24;
                #pragma unroll
                for (int cp2 = 0; cp2 < 4; ++cp2) {
                    ulonglong2 wL = *reinterpret_cast<const ulonglong2*>(wp + 2 * cp2);
                    ulonglong2 wC = *reinterpret_cast<const ulonglong2*>(wp + 8 + 2 * cp2);
                    ulonglong2 wR = *reinterpret_cast<const ulonglong2*>(wp + 16 + 2 * cp2);
                    conv_out(&acc0[cp2 * 4], caA, saA, r1A, wL, wC, wR);
                    conv_out(&acc1[cp2 * 4], caB, saB, r1B, wL, wC, wR);
                }
                if (kh < 2) {
                    caA = caB; saA = saB; r1A = r1B;
                    int off = (hr0 + kh + 2) * ROWP + w0;
                    caB = *reinterpret_cast<const ulonglong2*>(&scb[off]);
                    saB = *reinterpret_cast<const ulonglong2*>(&ssb[off]);
                    r1B = *reinterpret_cast<const u64*>(&ssb[off + 4]);
                }
            }
        }
    }

    // --- epilogue: activation chain + bias, vectorized coalesced stores ---
    #pragma unroll
    for (int co = 0; co < 8; ++co) {
        float bb = bias[co];
        const int cp2 = co >> 1, sub = (co & 1) * 2;
        const size_t cbase = ((size_t)((b * 8 + co) * 32 + dpos) << 14) + w0;
        #pragma unroll
        for (int o = 0; o < 2; ++o) {
            const u64* A = (o == 0) ? acc0 : acc1;
            float2 p0 = up2(A[cp2 * 4 + sub]);
            float2 p1 = up2(A[cp2 * 4 + sub + 1]);
            float4 r;
            r.x = act_chain(p0.x) + bb;
            r.y = act_chain(p0.y) + bb;
            r.z = act_chain(p1.x) + bb;
            r.w = act_chain(p1.y) + bb;
            *reinterpret_cast<float4*>(out + cbase + ((h0 + hr0 + o) << 7)) = r;
        }
    }
}

extern "C" void kernel_launch(void* const* d_in, const int* in_sizes, int n_in,
                              void* d_out, int out_size)
{
    const float* x    = (const float*)d_in[0];   // (8,8,32,128,128)
    const float* wgt  = (const float*)d_in[1];   // (8,8,3,3,3)
    const float* bias = (const float*)d_in[2];   // (8,1,1,1)
    float* out = (float*)d_out;                  // (8,8,32,128,128)

    weight_splat_kernel<<<1, 256>>>(wgt);
    void* gw_ptr = nullptr;
    cudaGetSymbolAddress(&gw_ptr, gW_buf);
    cudaMemcpyToSymbolAsync(cW, gw_ptr, 1728 * sizeof(u64), 0,
                            cudaMemcpyDeviceToDevice, 0);
    // grid = 16 H-tiles * 32 depths * 8 batches = 4096 blocks of 128 threads
    conv3d_fused_kernel<<<4096, 128>>>(x, bias, out);
}